// round 1
// baseline (speedup 1.0000x reference)
#include <cuda_runtime.h>

#define IH 256
#define IW 256
#define NPIX (IH * IW)          // 65536
#define NMAPS 88                // 8 * (10 + 1)
#define SRC_ELEMS (NPIX * 3)    // 196608

// Padded source: (h, w, [r,g,b,0]) — 1 MB, L2-resident scratch.
__device__ float4 g_src4[NPIX];

// Pack 3-channel source into float4-padded plane. One thread = 4 pixels
// (reads 3 aligned float4 = 12 floats, writes 4 float4).
__global__ void pack_src_kernel(const float* __restrict__ src) {
    int g = blockIdx.x * blockDim.x + threadIdx.x;   // group of 4 pixels
    if (g >= NPIX / 4) return;
    const float4* s4 = reinterpret_cast<const float4*>(src);
    float4 a = s4[g * 3 + 0];   // p0.r p0.g p0.b p1.r
    float4 b = s4[g * 3 + 1];   // p1.g p1.b p2.r p2.g
    float4 c = s4[g * 3 + 2];   // p2.b p3.r p3.g p3.b
    int p = g * 4;
    g_src4[p + 0] = make_float4(a.x, a.y, a.z, 0.f);
    g_src4[p + 1] = make_float4(a.w, b.x, b.y, 0.f);
    g_src4[p + 2] = make_float4(b.z, b.w, c.x, 0.f);
    g_src4[p + 3] = make_float4(c.y, c.z, c.w, 0.f);
}

__device__ __forceinline__ void sample_one(float gx, float gy, float* r) {
    // pixel-space coords: (g + 1) * 128 - 0.5
    float x = fmaf(gx, 128.f, 127.5f);
    float y = fmaf(gy, 128.f, 127.5f);
    float xw = floorf(x);
    float yn = floorf(y);
    float fx = x - xw;          // frac toward east
    float fy = y - yn;          // frac toward south

    // in-bounds masks: v > -1 && v < 256 (v is integral)
    float mw = (xw >= 0.f   && xw <= 255.f) ? 1.f : 0.f;
    float me = (xw >= -1.f  && xw <= 254.f) ? 1.f : 0.f;   // x_e = xw+1
    float mn = (yn >= 0.f   && yn <= 255.f) ? 1.f : 0.f;
    float ms = (yn >= -1.f  && yn <= 254.f) ? 1.f : 0.f;   // y_s = yn+1

    int xi = min(max(__float2int_rn(xw), 0), IW - 1);
    int xe = min(max(__float2int_rn(xw) + 1, 0), IW - 1);
    int yi = min(max(__float2int_rn(yn), 0), IH - 1);
    int ys = min(max(__float2int_rn(yn) + 1, 0), IH - 1);

    float wnw = (1.f - fy) * (1.f - fx) * (mn * mw);
    float wne = (1.f - fy) * fx         * (mn * me);
    float wsw = fy         * (1.f - fx) * (ms * mw);
    float wse = fy         * fx         * (ms * me);

    float4 vnw = __ldg(&g_src4[yi * IW + xi]);
    float4 vne = __ldg(&g_src4[yi * IW + xe]);
    float4 vsw = __ldg(&g_src4[ys * IW + xi]);
    float4 vse = __ldg(&g_src4[ys * IW + xe]);

    r[0] = wnw * vnw.x + wsw * vsw.x + wne * vne.x + wse * vse.x;
    r[1] = wnw * vnw.y + wsw * vsw.y + wne * vne.y + wse * vse.y;
    r[2] = wnw * vnw.z + wsw * vsw.z + wne * vne.z + wse * vse.z;
}

// One thread = 4 consecutive pixels of the flattened (NMAPS*NPIX) space.
// motions: (NMAPS, NPIX, 2) fp32; out: (NMAPS, NPIX, 3) fp32.
__global__ void __launch_bounds__(256) deform_kernel(
    const float* __restrict__ motions, float* __restrict__ out) {
    long long t = (long long)blockIdx.x * blockDim.x + threadIdx.x;
    const long long ngroups = (long long)NMAPS * NPIX / 4;
    if (t >= ngroups) return;

    const float4* m4 = reinterpret_cast<const float4*>(motions);
    float4 m0 = __ldg(&m4[t * 2 + 0]);   // x0 y0 x1 y1
    float4 m1 = __ldg(&m4[t * 2 + 1]);   // x2 y2 x3 y3

    float r[12];
    sample_one(m0.x, m0.y, r + 0);
    sample_one(m0.z, m0.w, r + 3);
    sample_one(m1.x, m1.y, r + 6);
    sample_one(m1.z, m1.w, r + 9);

    float4* o4 = reinterpret_cast<float4*>(out);
    o4[t * 3 + 0] = make_float4(r[0], r[1], r[2], r[3]);
    o4[t * 3 + 1] = make_float4(r[4], r[5], r[6], r[7]);
    o4[t * 3 + 2] = make_float4(r[8], r[9], r[10], r[11]);
}

extern "C" void kernel_launch(void* const* d_in, const int* in_sizes, int n_in,
                              void* d_out, int out_size) {
    // Identify inputs by element count (source = 196608, motions = 11534336).
    const float* source  = (const float*)d_in[0];
    const float* motions = (const float*)d_in[1];
    if (n_in >= 2 && in_sizes[0] != SRC_ELEMS) {
        source  = (const float*)d_in[1];
        motions = (const float*)d_in[0];
    }

    // Pack source into padded float4 plane (16384 groups of 4 pixels).
    pack_src_kernel<<<(NPIX / 4 + 255) / 256, 256>>>(source);

    // Main sampling pass: 88*65536/4 = 1,441,792 threads.
    const long long ngroups = (long long)NMAPS * NPIX / 4;
    int blocks = (int)((ngroups + 255) / 256);
    deform_kernel<<<blocks, 256>>>(motions, (float*)d_out);
}

// round 2
// speedup vs baseline: 1.6600x; 1.6600x over previous
#include <cuda_runtime.h>
#include <cuda_fp16.h>

#define IH 256
#define IW 256
#define NPIX (IH * IW)          // 65536
#define NMAPS 88                // 8 * (10 + 1)
#define SRC_ELEMS (NPIX * 3)    // 196608

// Vertical-pair packed fp16 source copies.
// Element (k, x) is 16B = two pixels (4 halves each: r,g,b,0).
// Copy A: pair k holds rows (2k, 2k+1),   k in [0,127]   -> 32768 elems
// Copy B: pair k holds rows (2k-1, 2k),   k in [0,128]   -> 33024 elems
//         (row -1 and row 256 are zero-filled)
__device__ uint4 g_srcA[128 * 256];
__device__ uint4 g_srcB[129 * 256];

__device__ __forceinline__ uint4 pack_pair(const float* src, int r0, int r1, int x) {
    __half h[8];
    if (r0 >= 0 && r0 < IH) {
        const float* p = src + (r0 * IW + x) * 3;
        h[0] = __float2half(p[0]); h[1] = __float2half(p[1]);
        h[2] = __float2half(p[2]); h[3] = __float2half(0.f);
    } else { h[0] = h[1] = h[2] = h[3] = __float2half(0.f); }
    if (r1 >= 0 && r1 < IH) {
        const float* p = src + (r1 * IW + x) * 3;
        h[4] = __float2half(p[0]); h[5] = __float2half(p[1]);
        h[6] = __float2half(p[2]); h[7] = __float2half(0.f);
    } else { h[4] = h[5] = h[6] = h[7] = __float2half(0.f); }
    return *reinterpret_cast<uint4*>(h);
}

__global__ void pack_src_kernel(const float* __restrict__ src) {
    int t = blockIdx.x * blockDim.x + threadIdx.x;
    if (t < 128 * 256) {
        int k = t >> 8, x = t & 255;
        g_srcA[t] = pack_pair(src, 2 * k, 2 * k + 1, x);
    }
    if (t < 129 * 256) {
        int k = t >> 8, x = t & 255;
        g_srcB[t] = pack_pair(src, 2 * k - 1, 2 * k, x);
    }
}

__device__ __forceinline__ void sample_one(float gx, float gy, float* r) {
    // pixel-space coords: (g + 1) * 128 - 0.5 ; gx,gy in [-1,1) -> x,y in [-0.5, 255.5)
    float x = fmaf(gx, 128.f, 127.5f);
    float y = fmaf(gy, 128.f, 127.5f);
    float xwf = floorf(x);
    float ynf = floorf(y);
    float fx = x - xwf;          // frac toward east
    float fy = y - ynf;          // frac toward south

    int xw = __float2int_rn(xwf);   // in [-1, 255]
    int yn = __float2int_rn(ynf);   // in [-1, 255]

    // masks (xw,yn in [-1,255] guaranteed by input range):
    float mw = (xw >= 0)        ? 1.f : 0.f;   // x_w in bounds
    float me = (xw <= IW - 2)   ? 1.f : 0.f;   // x_e = xw+1 in bounds
    float mn = (yn >= 0)        ? 1.f : 0.f;
    float ms = (yn <= IH - 2)   ? 1.f : 0.f;

    int xwc = max(xw, 0);
    int xec = min(xw + 1, IW - 1);

    // vertical-pair copy select: even yn -> A[yn>>1], odd yn -> B[(yn+1)>>1]
    bool odd = (yn & 1);
    const uint4* base = odd ? g_srcB : g_srcA;
    int k = odd ? ((yn + 1) >> 1) : (yn >> 1);   // A: [0,127], B: [0,128]
    int row = k * IW;

    uint4 wq = __ldg(&base[row + xwc]);   // (nw pixel, sw pixel)
    uint4 eq = __ldg(&base[row + xec]);   // (ne pixel, se pixel)

    float wnw = (1.f - fy) * (1.f - fx) * (mn * mw);
    float wne = (1.f - fy) * fx         * (mn * me);
    float wsw = fy         * (1.f - fx) * (ms * mw);
    float wse = fy         * fx         * (ms * me);

    float2 nw_rg = __half22float2(*reinterpret_cast<__half2*>(&wq.x));
    float2 nw_b_ = __half22float2(*reinterpret_cast<__half2*>(&wq.y));
    float2 sw_rg = __half22float2(*reinterpret_cast<__half2*>(&wq.z));
    float2 sw_b_ = __half22float2(*reinterpret_cast<__half2*>(&wq.w));
    float2 ne_rg = __half22float2(*reinterpret_cast<__half2*>(&eq.x));
    float2 ne_b_ = __half22float2(*reinterpret_cast<__half2*>(&eq.y));
    float2 se_rg = __half22float2(*reinterpret_cast<__half2*>(&eq.z));
    float2 se_b_ = __half22float2(*reinterpret_cast<__half2*>(&eq.w));

    r[0] = wnw * nw_rg.x + wsw * sw_rg.x + wne * ne_rg.x + wse * se_rg.x;
    r[1] = wnw * nw_rg.y + wsw * sw_rg.y + wne * ne_rg.y + wse * se_rg.y;
    r[2] = wnw * nw_b_.x + wsw * sw_b_.x + wne * ne_b_.x + wse * se_b_.x;
}

// One thread = 4 consecutive pixels of the flattened (NMAPS*NPIX) space.
__global__ void __launch_bounds__(256) deform_kernel(
    const float* __restrict__ motions, float* __restrict__ out) {
    long long t = (long long)blockIdx.x * blockDim.x + threadIdx.x;
    const long long ngroups = (long long)NMAPS * NPIX / 4;
    if (t >= ngroups) return;

    const float4* m4 = reinterpret_cast<const float4*>(motions);
    float4 m0 = __ldg(&m4[t * 2 + 0]);   // x0 y0 x1 y1
    float4 m1 = __ldg(&m4[t * 2 + 1]);   // x2 y2 x3 y3

    float r[12];
    sample_one(m0.x, m0.y, r + 0);
    sample_one(m0.z, m0.w, r + 3);
    sample_one(m1.x, m1.y, r + 6);
    sample_one(m1.z, m1.w, r + 9);

    float4* o4 = reinterpret_cast<float4*>(out);
    o4[t * 3 + 0] = make_float4(r[0], r[1], r[2], r[3]);
    o4[t * 3 + 1] = make_float4(r[4], r[5], r[6], r[7]);
    o4[t * 3 + 2] = make_float4(r[8], r[9], r[10], r[11]);
}

extern "C" void kernel_launch(void* const* d_in, const int* in_sizes, int n_in,
                              void* d_out, int out_size) {
    const float* source  = (const float*)d_in[0];
    const float* motions = (const float*)d_in[1];
    if (n_in >= 2 && in_sizes[0] != SRC_ELEMS) {
        source  = (const float*)d_in[1];
        motions = (const float*)d_in[0];
    }

    // Pack both vertical-pair copies (33024 threads covers A and B).
    pack_src_kernel<<<(129 * 256 + 255) / 256, 256>>>(source);

    const long long ngroups = (long long)NMAPS * NPIX / 4;
    int blocks = (int)((ngroups + 255) / 256);
    deform_kernel<<<blocks, 256>>>(motions, (float*)d_out);
}

// round 3
// speedup vs baseline: 1.9815x; 1.1937x over previous
#include <cuda_runtime.h>
#include <cuda_fp16.h>

#define IH 256
#define IW 256
#define NPIX (IH * IW)          // 65536
#define NMAPS 88                // 8 * (10 + 1)
#define SRC_ELEMS (NPIX * 3)    // 196608

#define QSTRIDE 132             // quads per row (padded for alignment)
#define QROWS 129
#define COPYSZ (QROWS * QSTRIDE)    // 17028 quads per parity copy

// One quad = 2x2 pixels, each pixel 4 fp16 (r,g,b,0) = 32 bytes.
// Local layout: [0..3]=(r0,c0) NW, [4..7]=(r0,c1) NE, [8..11]=(r1,c0) SW, [12..15]=(r1,c1) SE.
// Copy (py,px): quad (ky,kx) covers rows (2ky-py, 2ky-py+1), cols (2kx-px, 2kx-px+1).
// Out-of-bounds pixels are stored as ZERO (bakes in the reference's corner masks).
struct __align__(32) Quad { uint4 a, b; };
__device__ Quad g_quads[4 * COPYSZ];   // ~2.18 MB, L2-resident

__device__ __forceinline__ void px_fetch(const float* __restrict__ s, int r, int c, __half* out) {
    if ((unsigned)r < IH && (unsigned)c < IW) {
        const float* p = s + (r * IW + c) * 3;
        out[0] = __float2half(p[0]);
        out[1] = __float2half(p[1]);
        out[2] = __float2half(p[2]);
        out[3] = __float2half(0.f);
    } else {
        out[0] = out[1] = out[2] = out[3] = __float2half(0.f);
    }
}

__global__ void pack_src_kernel(const float* __restrict__ src) {
    int t = blockIdx.x * blockDim.x + threadIdx.x;
    if (t >= 4 * COPYSZ) return;
    int c   = t / COPYSZ;
    int rem = t % COPYSZ;
    int ky = rem / QSTRIDE;
    int kx = rem % QSTRIDE;
    int py = c >> 1, px = c & 1;
    int r0 = 2 * ky - py;
    int c0 = 2 * kx - px;

    __align__(32) __half h[16];
    px_fetch(src, r0,     c0,     h + 0);   // NW
    px_fetch(src, r0,     c0 + 1, h + 4);   // NE
    px_fetch(src, r0 + 1, c0,     h + 8);   // SW
    px_fetch(src, r0 + 1, c0 + 1, h + 12);  // SE
    g_quads[t] = *reinterpret_cast<Quad*>(h);
}

__device__ __forceinline__ float2 h2f(float v) {
    __half2 h = *reinterpret_cast<__half2*>(&v);
    return __half22float2(h);
}

// One thread = 4 consecutive pixels of the flattened (NMAPS*NPIX) space.
// Grid covers exactly 88*65536/4 = 1,441,792 threads (5632 blocks x 256).
__global__ void __launch_bounds__(256) deform_kernel(
    const float* __restrict__ motions, float* __restrict__ out) {
    int t = blockIdx.x * blockDim.x + threadIdx.x;

    const float4* m4 = reinterpret_cast<const float4*>(motions);
    float4 m0 = __ldg(&m4[(size_t)t * 2 + 0]);   // x0 y0 x1 y1
    float4 m1 = __ldg(&m4[(size_t)t * 2 + 1]);   // x2 y2 x3 y3

    float gx[4] = {m0.x, m0.z, m1.x, m1.z};
    float gy[4] = {m0.y, m0.w, m1.y, m1.w};

    float fx[4], fy[4];
    const Quad* qp[4];
#pragma unroll
    for (int s = 0; s < 4; s++) {
        // pixel-space: (g + 1) * 128 - 0.5, g in [-1,1) -> coord in [-0.5, 255.5)
        float x = fmaf(gx[s], 128.f, 127.5f);
        float y = fmaf(gy[s], 128.f, 127.5f);
        float xwf = floorf(x);
        float ynf = floorf(y);
        fx[s] = x - xwf;
        fy[s] = y - ynf;
        int xw = (int)xwf;     // [-1, 255]
        int yn = (int)ynf;     // [-1, 255]
        int py = yn & 1, px = xw & 1;
        int ky = (yn + py) >> 1;       // [0,128]
        int kx = (xw + px) >> 1;       // [0,128]
        qp[s] = &g_quads[((py << 1) | px) * COPYSZ + ky * QSTRIDE + kx];
    }

    // 4 independent 256-bit gathers (one line-touch / one 32B sector each).
    float q[4][8];
#pragma unroll
    for (int s = 0; s < 4; s++) {
        asm("ld.global.v8.f32 {%0,%1,%2,%3,%4,%5,%6,%7}, [%8];"
            : "=f"(q[s][0]), "=f"(q[s][1]), "=f"(q[s][2]), "=f"(q[s][3]),
              "=f"(q[s][4]), "=f"(q[s][5]), "=f"(q[s][6]), "=f"(q[s][7])
            : "l"(qp[s]));
    }

    float r[12];
#pragma unroll
    for (int s = 0; s < 4; s++) {
        float wnw = (1.f - fy[s]) * (1.f - fx[s]);
        float wne = (1.f - fy[s]) * fx[s];
        float wsw = fy[s] * (1.f - fx[s]);
        float wse = fy[s] * fx[s];

        float2 nw = h2f(q[s][0]);
        float2 ne = h2f(q[s][2]);
        float2 sw = h2f(q[s][4]);
        float2 se = h2f(q[s][6]);
        float nwb = h2f(q[s][1]).x;
        float neb = h2f(q[s][3]).x;
        float swb = h2f(q[s][5]).x;
        float seb = h2f(q[s][7]).x;

        r[s * 3 + 0] = wnw * nw.x + wne * ne.x + wsw * sw.x + wse * se.x;
        r[s * 3 + 1] = wnw * nw.y + wne * ne.y + wsw * sw.y + wse * se.y;
        r[s * 3 + 2] = wnw * nwb  + wne * neb  + wsw * swb  + wse * seb;
    }

    float4* o4 = reinterpret_cast<float4*>(out);
    size_t tt = t;
    o4[tt * 3 + 0] = make_float4(r[0], r[1], r[2],  r[3]);
    o4[tt * 3 + 1] = make_float4(r[4], r[5], r[6],  r[7]);
    o4[tt * 3 + 2] = make_float4(r[8], r[9], r[10], r[11]);
}

extern "C" void kernel_launch(void* const* d_in, const int* in_sizes, int n_in,
                              void* d_out, int out_size) {
    const float* source  = (const float*)d_in[0];
    const float* motions = (const float*)d_in[1];
    if (n_in >= 2 && in_sizes[0] != SRC_ELEMS) {
        source  = (const float*)d_in[1];
        motions = (const float*)d_in[0];
    }

    pack_src_kernel<<<(4 * COPYSZ + 255) / 256, 256>>>(source);

    const int ngroups = NMAPS * NPIX / 4;     // 1,441,792
    deform_kernel<<<ngroups / 256, 256>>>(motions, (float*)d_out);
}